// round 15
// baseline (speedup 1.0000x reference)
#include <cuda_runtime.h>
#include <cuda_fp16.h>
#include <cstdint>

namespace {
constexpr int DM     = 1024;
constexpr int SEQ    = 2048;
constexpr int NBATCH = 2;
constexpr int TOK    = SEQ * NBATCH;   // 4096
constexpr int NVOCAB = 32000;
constexpr float O_SCALE     = 512.f;   // O stored as O/512 in fp16 (exact pow2)
constexpr float O_SCALE_INV = 1.f / 512.f;
constexpr int NTHR = 512;              // 16 warps
}

// ---- scratch (device globals: allocation-free) ----
__device__ __half g_eh[TOK * DM];              // gathered embeddings, fp16
__device__ __half g_QKh[TOK * 2 * DM];         // [t][0:1024]=Q, [t][1024:2048]=K
__device__ __half g_Vt[DM * TOK];              // V transposed: Vt[d][b*SEQ+t]
__device__ __half g_Sh[NBATCH * SEQ * SEQ];    // causal scores, fp16
__device__ __half g_Oh[TOK * DM];              // attention out / 512, fp16
__device__ __half g_Wh[NVOCAB * DM];           // fp16 wo
__device__ __half g_Wqk[2 * DM * DM];          // [wq; wk] fp16
__device__ __half g_Wv[DM * DM];
__device__ float  g_bqk[2 * DM];               // [bq; bk]
__device__ float  g_P1[TOK * DM];              // AV partial (seg0), f32
__device__ float  g_P2[2048 * DM];             // AV partial (seg1, rows i>=8), f32

__device__ __forceinline__ uint32_t smem_u32(const void* p) {
    uint32_t a;
    asm("{ .reg .u64 t; cvta.to.shared.u64 t, %1; cvt.u32.u64 %0, t; }" : "=r"(a) : "l"(p));
    return a;
}

__device__ __forceinline__ void mma16h(float* c, const uint32_t* a, const uint32_t* b) {
    asm volatile(
        "mma.sync.aligned.m16n8k16.row.col.f32.f16.f16.f32 "
        "{%0,%1,%2,%3}, {%4,%5,%6,%7}, {%8,%9}, {%0,%1,%2,%3};\n"
        : "+f"(c[0]), "+f"(c[1]), "+f"(c[2]), "+f"(c[3])
        : "r"(a[0]), "r"(a[1]), "r"(a[2]), "r"(a[3]), "r"(b[0]), "r"(b[1]));
}

__device__ __forceinline__ void ldsm4(uint32_t* r, uint32_t addr) {
    asm volatile("ldmatrix.sync.aligned.m8n8.x4.shared.b16 {%0,%1,%2,%3}, [%4];"
        : "=r"(r[0]), "=r"(r[1]), "=r"(r[2]), "=r"(r[3]) : "r"(addr));
}

__device__ __forceinline__ void cp16(uint32_t smem, const void* g) {
    asm volatile("cp.async.cg.shared.global [%0], [%1], 16;" :: "r"(smem), "l"(g) : "memory");
}

// ---- tile constants: 128x256 CTA tile, K-chunk 64, 3 stages ----
namespace lh {
constexpr int PITCH     = 144;                // 128B data (64 fp16) + 16B pad
constexpr int A_BYTES   = 128 * PITCH;        // 18432
constexpr int B_BYTES   = 256 * PITCH;        // 36864
constexpr int STG_BYTES = A_BYTES + B_BYTES;  // 55296
constexpr int SMEM_TOT  = 3 * STG_BYTES;      // 165888
}

// ============================================================================
// Unified fp16 NT GEMM, 512 threads, warp tile 64x32 (2x8 warps):
// EPI: 0 = +colbias then elu+1, 2 = causal mask (1D triangular grid),
//      5 = +rowbias.
// For EPI==2 the grid is (72, 1, NBATCH): blockIdx.x enumerates exactly the
// lower-triangle tiles (per 128-row i: j <= i/2; count i/2+1; total 72).
// ============================================================================
template<int EPI>
__global__ void __launch_bounds__(NTHR, 1)
gemm_h(const __half* __restrict__ A, int lda,
       const __half* __restrict__ B, int ldb,
       const float* __restrict__ bias,
       __half* __restrict__ C, int ldc,
       int K, long long Az, long long Bz, long long Cz)
{
    A += (size_t)blockIdx.z * Az;
    B += (size_t)blockIdx.z * Bz;
    C += (size_t)blockIdx.z * Cz;

    int bm, bn;
    if (EPI == 2) {
        const int t = blockIdx.x;       // 0..71
        int i = 0, c = 0;
        for (;; i++) {
            int ci = (i >> 1) + 1;
            if (c + ci > t) break;
            c += ci;
        }
        bm = i * 128;
        bn = (t - c) * 256;
    } else {
        bm = blockIdx.x * 128;
        bn = blockIdx.y * 256;
    }

    extern __shared__ char smem[];
    const uint32_t sb = smem_u32(smem);
    const int tid  = threadIdx.x;
    const int lane = tid & 31;
    const int warp = tid >> 5;
    const int wm   = (warp >> 3) * 64;   // 2 warp rows
    const int wn   = (warp & 7) * 32;    // 8 warp cols

    const int g = lane >> 3;
    const uint32_t frOff = (uint32_t)(((lane & 7) + (g & 1) * 8) * lh::PITCH + (g >> 1) * 16);

    float acc[4][4][4];
    #pragma unroll
    for (int mt = 0; mt < 4; mt++)
        #pragma unroll
        for (int nt = 0; nt < 4; nt++)
            #pragma unroll
            for (int r = 0; r < 4; r++) acc[mt][nt][r] = 0.f;

    const __half* Ag = A + (size_t)bm * lda;
    const __half* Bg = B + (size_t)bn * ldb;

    const int nk = K / 64;

    auto load_stage = [&](int st) {
        const uint32_t base = sb + (st % 3) * lh::STG_BYTES;
        const int kb = st * 64;
        #pragma unroll
        for (int i = 0; i < 2; i++) {               // A: 128 rows x 8 16B chunks
            int idx = tid + i * NTHR;
            int row = idx >> 3, ch = idx & 7;
            cp16(base + row * lh::PITCH + ch * 16, Ag + (size_t)row * lda + kb + ch * 8);
        }
        const uint32_t bb = base + lh::A_BYTES;
        #pragma unroll
        for (int i = 0; i < 4; i++) {               // B: 256 rows x 8 16B chunks
            int idx = tid + i * NTHR;
            int row = idx >> 3, ch = idx & 7;
            cp16(bb + row * lh::PITCH + ch * 16, Bg + (size_t)row * ldb + kb + ch * 8);
        }
        asm volatile("cp.async.commit_group;" ::: "memory");
    };

    load_stage(0);
    if (nk > 1) load_stage(1); else asm volatile("cp.async.commit_group;" ::: "memory");

    for (int ck = 0; ck < nk; ck++) {
        // committed = 2 + ck; wait_group 1 => complete >= ck+1 (stage ck ready)
        asm volatile("cp.async.wait_group 1;" ::: "memory");
        __syncthreads();
        if (ck + 2 < nk) load_stage(ck + 2);
        else asm volatile("cp.async.commit_group;" ::: "memory");

        const uint32_t sa  = sb + (ck % 3) * lh::STG_BYTES;
        const uint32_t sbb = sa + lh::A_BYTES;
        #pragma unroll
        for (int ks = 0; ks < 4; ks++) {            // four k16 steps per chunk
            uint32_t af[4][4], bf[4][2];
            #pragma unroll
            for (int mt = 0; mt < 4; mt++)
                ldsm4(af[mt], sa + (wm + mt * 16) * lh::PITCH + ks * 32 + frOff);
            #pragma unroll
            for (int p = 0; p < 2; p++) {
                uint32_t t4[4];
                ldsm4(t4, sbb + (wn + p * 16) * lh::PITCH + ks * 32 + frOff);
                bf[2 * p][0]     = t4[0]; bf[2 * p][1]     = t4[2];
                bf[2 * p + 1][0] = t4[1]; bf[2 * p + 1][1] = t4[3];
            }
            #pragma unroll
            for (int mt = 0; mt < 4; mt++)
                #pragma unroll
                for (int nt = 0; nt < 4; nt++)
                    mma16h(acc[mt][nt], af[mt], bf[nt]);
        }
    }

    #pragma unroll
    for (int mt = 0; mt < 4; mt++) {
        #pragma unroll
        for (int nt = 0; nt < 4; nt++) {
            int r = bm + wm + mt * 16 + (lane >> 2);
            int c = bn + wn + nt * 8 + ((lane & 3) << 1);
            float v[4] = {acc[mt][nt][0], acc[mt][nt][1], acc[mt][nt][2], acc[mt][nt][3]};
            if (EPI == 0) {
                float b0 = bias[c], b1 = bias[c + 1];
                v[0] += b0; v[1] += b1; v[2] += b0; v[3] += b1;
                #pragma unroll
                for (int j = 0; j < 4; j++)
                    v[j] = (v[j] > 0.f) ? (v[j] + 1.f) : expf(v[j]);
            } else if (EPI == 5) {
                float b0 = bias[r], b1 = bias[r + 8];
                v[0] += b0; v[1] += b0; v[2] += b1; v[3] += b1;
            } else if (EPI == 2) {
                if (c     > r)     v[0] = 0.f;
                if (c + 1 > r)     v[1] = 0.f;
                if (c     > r + 8) v[2] = 0.f;
                if (c + 1 > r + 8) v[3] = 0.f;
            }
            *(__half2*)&C[(size_t)r * ldc + c]       = __floats2half2_rn(v[0], v[1]);
            *(__half2*)&C[(size_t)(r + 8) * ldc + c] = __floats2half2_rn(v[2], v[3]);
        }
    }
}

// ============================================================================
// Split-K AV kernel: O_partials = S @ Vt^T per batch, triangular K.
// Tile bm_idx i needs nk = 2(i+1) chunks; split at chunk 16:
//   seg0 (chunks [0, min(nk,16)))    -> P1 (all 16 tiles)
//   seg1 (chunks [16, nk), i >= 8)   -> P2
// Grid = 192 = 24 segments x 8 (bn in 0..3, z in 0..1), blockIdx.x = s*8+grp,
// segments sorted longest-first so wave 1 holds all 16-chunk segments.
// ============================================================================
__global__ void __launch_bounds__(NTHR, 1)
av_split(const __half* __restrict__ S, const __half* __restrict__ Vt,
         float* __restrict__ P1, float* __restrict__ P2)
{
    const int b   = blockIdx.x;
    const int grp = b & 7;
    const int s   = b >> 3;          // 0..23, sorted desc by length
    const int bn  = (grp >> 1) * 256;
    const int z   = grp & 1;

    int i, kb0, len, buf;
    if (s < 8)            { i = 8 + s;          kb0 = 0;  len = 16;            buf = 0; }
    else if ((s & 1) == 0){ i = (22 - s) >> 1;  kb0 = 0;  len = 2 * (i + 1);   buf = 0;
                            if (len > 16) len = 16; }
    else                  { i = (39 - s) >> 1;  kb0 = 16; len = 2 * (i + 1) - 16; buf = 1; }

    const int bm = i * 128;

    extern __shared__ char smem[];
    const uint32_t sb = smem_u32(smem);
    const int tid  = threadIdx.x;
    const int lane = tid & 31;
    const int warp = tid >> 5;
    const int wm   = (warp >> 3) * 64;
    const int wn   = (warp & 7) * 32;

    const int g = lane >> 3;
    const uint32_t frOff = (uint32_t)(((lane & 7) + (g & 1) * 8) * lh::PITCH + (g >> 1) * 16);

    float acc[4][4][4];
    #pragma unroll
    for (int mt = 0; mt < 4; mt++)
        #pragma unroll
        for (int nt = 0; nt < 4; nt++)
            #pragma unroll
            for (int r = 0; r < 4; r++) acc[mt][nt][r] = 0.f;

    const __half* Ag = S  + (size_t)z * SEQ * SEQ + (size_t)bm * SEQ;
    const __half* Bg = Vt + (size_t)bn * TOK + (size_t)z * SEQ;

    auto load_stage = [&](int st) {
        const uint32_t base = sb + (st % 3) * lh::STG_BYTES;
        const int kb = (kb0 + st) * 64;
        #pragma unroll
        for (int ii = 0; ii < 2; ii++) {
            int idx = tid + ii * NTHR;
            int row = idx >> 3, ch = idx & 7;
            cp16(base + row * lh::PITCH + ch * 16, Ag + (size_t)row * SEQ + kb + ch * 8);
        }
        const uint32_t bb = base + lh::A_BYTES;
        #pragma unroll
        for (int ii = 0; ii < 4; ii++) {
            int idx = tid + ii * NTHR;
            int row = idx >> 3, ch = idx & 7;
            cp16(bb + row * lh::PITCH + ch * 16, Bg + (size_t)row * TOK + kb + ch * 8);
        }
        asm volatile("cp.async.commit_group;" ::: "memory");
    };

    load_stage(0);
    if (len > 1) load_stage(1); else asm volatile("cp.async.commit_group;" ::: "memory");

    for (int ck = 0; ck < len; ck++) {
        asm volatile("cp.async.wait_group 1;" ::: "memory");
        __syncthreads();
        if (ck + 2 < len) load_stage(ck + 2);
        else asm volatile("cp.async.commit_group;" ::: "memory");

        const uint32_t sa  = sb + (ck % 3) * lh::STG_BYTES;
        const uint32_t sbb = sa + lh::A_BYTES;
        #pragma unroll
        for (int ks = 0; ks < 4; ks++) {
            uint32_t af[4][4], bf[4][2];
            #pragma unroll
            for (int mt = 0; mt < 4; mt++)
                ldsm4(af[mt], sa + (wm + mt * 16) * lh::PITCH + ks * 32 + frOff);
            #pragma unroll
            for (int p = 0; p < 2; p++) {
                uint32_t t4[4];
                ldsm4(t4, sbb + (wn + p * 16) * lh::PITCH + ks * 32 + frOff);
                bf[2 * p][0]     = t4[0]; bf[2 * p][1]     = t4[2];
                bf[2 * p + 1][0] = t4[1]; bf[2 * p + 1][1] = t4[3];
            }
            #pragma unroll
            for (int mt = 0; mt < 4; mt++)
                #pragma unroll
                for (int nt = 0; nt < 4; nt++)
                    mma16h(acc[mt][nt], af[mt], bf[nt]);
        }
    }

    // f32 partial store
    float* P = buf ? P2 : P1;
    const size_t rowbase = buf ? (size_t)(z * 1024 + (i - 8) * 128)
                               : (size_t)(z * 2048 + i * 128);
    #pragma unroll
    for (int mt = 0; mt < 4; mt++) {
        #pragma unroll
        for (int nt = 0; nt < 4; nt++) {
            size_t r = rowbase + wm + mt * 16 + (lane >> 2);
            int    c = bn + wn + nt * 8 + ((lane & 3) << 1);
            *(float2*)&P[r * DM + c]       = make_float2(acc[mt][nt][0], acc[mt][nt][1]);
            *(float2*)&P[(r + 8) * DM + c] = make_float2(acc[mt][nt][2], acc[mt][nt][3]);
        }
    }
}

// Combine: Oh = fp16((P1 + P2[if row-block >= 8]) / 512)
__global__ void __launch_bounds__(256)
av_combine(const float* __restrict__ P1, const float* __restrict__ P2,
           __half* __restrict__ Oh)
{
    size_t flat = ((size_t)blockIdx.x * 256 + threadIdx.x) * 4;
    int t = (int)(flat >> 10);          // token row
    int d = (int)(flat & 1023);
    int z = t >> 11;
    int r = t & 2047;
    float4 v = *(const float4*)(P1 + flat);
    if (r >= 1024) {
        const float4 w = *(const float4*)(P2 + (size_t)(z * 1024 + r - 1024) * DM + d);
        v.x += w.x; v.y += w.y; v.z += w.z; v.w += w.w;
    }
    __half2 h0 = __floats2half2_rn(v.x * O_SCALE_INV, v.y * O_SCALE_INV);
    __half2 h1 = __floats2half2_rn(v.z * O_SCALE_INV, v.w * O_SCALE_INV);
    uint2 u;
    u.x = *(uint32_t*)&h0;
    u.y = *(uint32_t*)&h1;
    *(uint2*)(Oh + flat) = u;
}

// ============================================================================
// PERSISTENT fp16 logits GEMM, 512 threads:
// C[4096,32000] = (A/512)h @ Bh^T * 512 + bias.
// Tile map: tile t -> bm = (t % 32)*128, bn = (t / 32)*256.  16 chunks/tile.
// ============================================================================
__global__ void __launch_bounds__(NTHR, 1)
logits_persist(const __half* __restrict__ A, const __half* __restrict__ B,
               const float* __restrict__ bias, float* __restrict__ C,
               int ntiles, int gridsz)
{
    extern __shared__ char smem[];
    const uint32_t sb = smem_u32(smem);
    const int tid  = threadIdx.x;
    const int lane = tid & 31;
    const int warp = tid >> 5;
    const int wm   = (warp >> 3) * 64;
    const int wn   = (warp & 7) * 32;

    const int g = lane >> 3;
    const uint32_t frOff = (uint32_t)(((lane & 7) + (g & 1) * 8) * lh::PITCH + (g >> 1) * 16);

    if ((int)blockIdx.x >= ntiles) return;
    const int nt_mine = (ntiles - (int)blockIdx.x + gridsz - 1) / gridsz;
    const int NC = nt_mine * 16;

    float acc[4][4][4];
    #pragma unroll
    for (int mt = 0; mt < 4; mt++)
        #pragma unroll
        for (int nt = 0; nt < 4; nt++)
            #pragma unroll
            for (int r = 0; r < 4; r++) acc[mt][nt][r] = 0.f;

    auto load_chunk = [&](int cg) {
        const int tile = (int)blockIdx.x + (cg >> 4) * gridsz;
        const int bm = (tile & 31) << 7;
        const int bn = (tile >> 5) << 8;
        const int kb = (cg & 15) << 6;
        const __half* Ag = A + (size_t)bm * DM + kb;
        const __half* Bg = B + (size_t)bn * DM + kb;
        const uint32_t base = sb + (cg % 3) * lh::STG_BYTES;
        #pragma unroll
        for (int i = 0; i < 2; i++) {
            int idx = tid + i * NTHR;
            int row = idx >> 3, ch = idx & 7;
            cp16(base + row * lh::PITCH + ch * 16, Ag + (size_t)row * DM + ch * 8);
        }
        const uint32_t bb = base + lh::A_BYTES;
        #pragma unroll
        for (int i = 0; i < 4; i++) {
            int idx = tid + i * NTHR;
            int row = idx >> 3, ch = idx & 7;
            cp16(bb + row * lh::PITCH + ch * 16, Bg + (size_t)row * DM + ch * 8);
        }
        asm volatile("cp.async.commit_group;" ::: "memory");
    };

    load_chunk(0); load_chunk(1);   // NC >= 16, always valid

    for (int cg = 0; cg < NC; cg++) {
        asm volatile("cp.async.wait_group 1;" ::: "memory");
        __syncthreads();
        if (cg + 2 < NC) load_chunk(cg + 2);
        else asm volatile("cp.async.commit_group;" ::: "memory");

        const uint32_t sa  = sb + (cg % 3) * lh::STG_BYTES;
        const uint32_t sbb = sa + lh::A_BYTES;
        #pragma unroll
        for (int ks = 0; ks < 4; ks++) {
            uint32_t af[4][4], bf[4][2];
            #pragma unroll
            for (int mt = 0; mt < 4; mt++)
                ldsm4(af[mt], sa + (wm + mt * 16) * lh::PITCH + ks * 32 + frOff);
            #pragma unroll
            for (int p = 0; p < 2; p++) {
                uint32_t t4[4];
                ldsm4(t4, sbb + (wn + p * 16) * lh::PITCH + ks * 32 + frOff);
                bf[2 * p][0]     = t4[0]; bf[2 * p][1]     = t4[2];
                bf[2 * p + 1][0] = t4[1]; bf[2 * p + 1][1] = t4[3];
            }
            #pragma unroll
            for (int mt = 0; mt < 4; mt++)
                #pragma unroll
                for (int nt = 0; nt < 4; nt++)
                    mma16h(acc[mt][nt], af[mt], bf[nt]);
        }

        if ((cg & 15) == 15) {
            const int tile = (int)blockIdx.x + (cg >> 4) * gridsz;
            const int bm = (tile & 31) << 7;
            const int bn = (tile >> 5) << 8;
            #pragma unroll
            for (int mt = 0; mt < 4; mt++) {
                #pragma unroll
                for (int nt = 0; nt < 4; nt++) {
                    int r = bm + wm + mt * 16 + (lane >> 2);
                    int c = bn + wn + nt * 8 + ((lane & 3) << 1);
                    const float2 bv = *(const float2*)(bias + c);
                    *(float2*)&C[(size_t)r * NVOCAB + c] = make_float2(
                        acc[mt][nt][0] * O_SCALE + bv.x,
                        acc[mt][nt][1] * O_SCALE + bv.y);
                    *(float2*)&C[(size_t)(r + 8) * NVOCAB + c] = make_float2(
                        acc[mt][nt][2] * O_SCALE + bv.x,
                        acc[mt][nt][3] * O_SCALE + bv.y);
                    acc[mt][nt][0] = 0.f; acc[mt][nt][1] = 0.f;
                    acc[mt][nt][2] = 0.f; acc[mt][nt][3] = 0.f;
                }
            }
        }
    }
}

// ============================================================================
// wo -> fp16: high-ILP streaming (32 elems/thread, 8 independent float4 loads).
// 4000 SHORT blocks on the LOWEST-priority stream: they can only dispatch when
// an SM has free resources; GEMM CTAs (full RF) always win, so these backfill
// idle SMs (QK wave-2, Vt, Sc remainders) and inter-kernel gaps.
// ============================================================================
__global__ void __launch_bounds__(256)
cvt_wo(const float* __restrict__ in, __half* __restrict__ out)
{
    size_t i = ((size_t)blockIdx.x * 256 + threadIdx.x) * 32;
    float4 v[8];
    #pragma unroll
    for (int p = 0; p < 8; p++) v[p] = *(const float4*)(in + i + p * 4);   // MLP=8
    #pragma unroll
    for (int p = 0; p < 4; p++) {
        __half2 h[4];
        h[0] = __floats2half2_rn(v[2 * p].x,     v[2 * p].y);
        h[1] = __floats2half2_rn(v[2 * p].z,     v[2 * p].w);
        h[2] = __floats2half2_rn(v[2 * p + 1].x, v[2 * p + 1].y);
        h[3] = __floats2half2_rn(v[2 * p + 1].z, v[2 * p + 1].w);
        *(uint4*)(out + i + p * 8) = *(uint4*)h;
    }
}

// ============================================================================
// Fused prep kernel (small): wq/wk/wv->fp16, bias concat, embed gather+cvt.
// ============================================================================
namespace prep {
constexpr int W_BLK    = DM * DM / (256 * 16);       // 256
constexpr int QKV_END  = 3 * W_BLK;                  // 768
constexpr int GATH_END = QKV_END + TOK;              // 4864
constexpr int TOTAL    = GATH_END + 2 * DM / 256;    // 4872
}

__global__ void __launch_bounds__(256)
prep_small(const float* __restrict__ wq, const float* __restrict__ wk,
           const float* __restrict__ wv,
           const float* __restrict__ bq, const float* __restrict__ bk,
           const int* __restrict__ x, const float* __restrict__ emb,
           __half* __restrict__ Wqk, __half* __restrict__ Wvh,
           float* __restrict__ bqk, __half* __restrict__ eh)
{
    const int b = blockIdx.x;
    if (b < prep::QKV_END) {
        int mat = b / prep::W_BLK;
        size_t base = (size_t)(b % prep::W_BLK);
        const float* in  = (mat == 0) ? wq : (mat == 1) ? wk : wv;
        __half* out = (mat == 0) ? Wqk : (mat == 1) ? (Wqk + (size_t)DM * DM) : Wvh;
        size_t i = (base * 256 + threadIdx.x) * 16;
        float4 v[4];
        #pragma unroll
        for (int p = 0; p < 4; p++) v[p] = *(const float4*)(in + i + p * 4);
        #pragma unroll
        for (int p = 0; p < 2; p++) {
            __half2 h[4];
            h[0] = __floats2half2_rn(v[2 * p].x,     v[2 * p].y);
            h[1] = __floats2half2_rn(v[2 * p].z,     v[2 * p].w);
            h[2] = __floats2half2_rn(v[2 * p + 1].x, v[2 * p + 1].y);
            h[3] = __floats2half2_rn(v[2 * p + 1].z, v[2 * p + 1].w);
            *(uint4*)(out + i + p * 8) = *(uint4*)h;
        }
    } else if (b < prep::GATH_END) {
        const int t = b - prep::QKV_END;
        const int d = threadIdx.x * 4;
        const float4 v = *(const float4*)(emb + (size_t)x[t] * DM + d);
        __half2 h0 = __floats2half2_rn(v.x, v.y);
        __half2 h1 = __floats2half2_rn(v.z, v.w);
        uint2 u;
        u.x = *(uint32_t*)&h0;
        u.y = *(uint32_t*)&h1;
        *(uint2*)(eh + (size_t)t * DM + d) = u;
    } else {
        int i = (b - prep::GATH_END) * 256 + threadIdx.x;
        bqk[i] = (i < DM) ? bq[i] : bk[i - DM];
    }
}

extern "C" void kernel_launch(void* const* d_in, const int* in_sizes, int n_in,
                              void* d_out, int out_size)
{
    (void)in_sizes; (void)n_in; (void)out_size;
    const int*   x   = (const int*)  d_in[0];
    const float* emb = (const float*)d_in[1];
    const float* wq  = (const float*)d_in[2];
    const float* bq  = (const float*)d_in[3];
    const float* wk  = (const float*)d_in[4];
    const float* bk  = (const float*)d_in[5];
    const float* wv  = (const float*)d_in[6];
    const float* bv  = (const float*)d_in[7];
    const float* wo  = (const float*)d_in[8];
    const float* bo  = (const float*)d_in[9];
    float* out = (float*)d_out;

    __half *eh, *QKh, *Vt, *Sh, *Oh, *Wh, *Wqk, *Wv;
    float *bqk, *P1, *P2;
    cudaGetSymbolAddress((void**)&eh,  g_eh);
    cudaGetSymbolAddress((void**)&QKh, g_QKh);
    cudaGetSymbolAddress((void**)&Vt,  g_Vt);
    cudaGetSymbolAddress((void**)&Sh,  g_Sh);
    cudaGetSymbolAddress((void**)&Oh,  g_Oh);
    cudaGetSymbolAddress((void**)&Wh,  g_Wh);
    cudaGetSymbolAddress((void**)&Wqk, g_Wqk);
    cudaGetSymbolAddress((void**)&Wv,  g_Wv);
    cudaGetSymbolAddress((void**)&bqk, g_bqk);
    cudaGetSymbolAddress((void**)&P1,  g_P1);
    cudaGetSymbolAddress((void**)&P2,  g_P2);

    int nsm = 148;
    cudaDeviceGetAttribute(&nsm, cudaDevAttrMultiProcessorCount, 0);

    // lowest-priority side stream + events (created once, on uncaptured call)
    static cudaStream_t s2 = nullptr;
    static cudaEvent_t evFork = nullptr, evJoin = nullptr;
    if (s2 == nullptr) {
        int prLo = 0, prHi = 0;
        cudaDeviceGetStreamPriorityRange(&prLo, &prHi);   // prLo = least priority
        cudaStreamCreateWithPriority(&s2, cudaStreamNonBlocking, prLo);
        cudaEventCreateWithFlags(&evFork, cudaEventDisableTiming);
        cudaEventCreateWithFlags(&evJoin, cudaEventDisableTiming);
    }

    cudaFuncSetAttribute(logits_persist,
                         cudaFuncAttributeMaxDynamicSharedMemorySize, lh::SMEM_TOT);
    cudaFuncSetAttribute(av_split,
                         cudaFuncAttributeMaxDynamicSharedMemorySize, lh::SMEM_TOT);
    cudaFuncSetAttribute(gemm_h<0>,
                         cudaFuncAttributeMaxDynamicSharedMemorySize, lh::SMEM_TOT);
    cudaFuncSetAttribute(gemm_h<5>,
                         cudaFuncAttributeMaxDynamicSharedMemorySize, lh::SMEM_TOT);
    cudaFuncSetAttribute(gemm_h<2>,
                         cudaFuncAttributeMaxDynamicSharedMemorySize, lh::SMEM_TOT);

    dim3 thr(256), thrG(NTHR);

    // fork: wo conversion on lowest-priority stream as 4000 SHORT blocks
    cudaEventRecord(evFork, 0);
    cudaStreamWaitEvent(s2, evFork, 0);
    cvt_wo<<<NVOCAB * DM / (256 * 32), thr, 0, s2>>>(wo, Wh);
    cudaEventRecord(evJoin, s2);

    // 0) small prep: qkv weights, gather, bias concat
    prep_small<<<prep::TOTAL, thr>>>(wq, wk, wv, bq, bk, x, emb, Wqk, Wv, bqk, eh);

    // 1) fused Q+K projection: QKh[4096,2048] = e_h @ Wqk^T, elu+1 + bias
    dim3 gQK(TOK / 128, 2 * DM / 256, 1);
    gemm_h<0><<<gQK, thrG, lh::SMEM_TOT>>>(eh, DM, Wqk, DM, bqk, QKh, 2 * DM, DM, 0, 0, 0);

    // 2) V pre-transposed: Vt[1024,4096] = wv @ e_h^T + bv (row bias)
    dim3 gVt(DM / 128, TOK / 256, 1);
    gemm_h<5><<<gVt, thrG, lh::SMEM_TOT>>>(Wv, DM, eh, DM, bv, Vt, TOK, DM, 0, 0, 0);

    // 3) causal scores: exact triangular grid (72 live tiles per batch, 1 wave)
    dim3 gSc(72, 1, NBATCH);
    gemm_h<2><<<gSc, thrG, lh::SMEM_TOT>>>(
        QKh, 2 * DM, QKh + DM, 2 * DM, nullptr, Sh, SEQ, DM,
        (long long)SEQ * 2 * DM, (long long)SEQ * 2 * DM, (long long)SEQ * SEQ);

    // 4) AV with split-K load balancing (192 segments, longest-first)
    av_split<<<192, thrG, lh::SMEM_TOT>>>(Sh, Vt, P1, P2);
    av_combine<<<TOK * DM / (256 * 4), thr>>>(P1, P2, Oh);

    // join: wo conversion must be done before logits reads Wh
    cudaStreamWaitEvent(0, evJoin, 0);

    // 5) logits (persistent): [4096,32000] = (Oh @ Wh^T) * 512 + bo
    const int ntiles = (TOK / 128) * (NVOCAB / 256);   // 4000
    logits_persist<<<nsm, thrG, lh::SMEM_TOT>>>(Oh, Wh, bo, out, ntiles, nsm);
}

// round 16
// speedup vs baseline: 1.0103x; 1.0103x over previous
#include <cuda_runtime.h>
#include <cuda_fp16.h>
#include <cstdint>

namespace {
constexpr int DM     = 1024;
constexpr int SEQ    = 2048;
constexpr int NBATCH = 2;
constexpr int TOK    = SEQ * NBATCH;   // 4096
constexpr int NVOCAB = 32000;
constexpr float O_SCALE     = 512.f;   // O stored as O/512 in fp16 (exact pow2)
constexpr float O_SCALE_INV = 1.f / 512.f;
constexpr int NTHR = 512;              // 16 warps
}

// ---- scratch (device globals: allocation-free) ----
__device__ __half g_eh[TOK * DM];              // gathered embeddings, fp16
__device__ __half g_QKh[TOK * 2 * DM];         // [t][0:1024]=Q, [t][1024:2048]=K
__device__ __half g_Vt[DM * TOK];              // V transposed: Vt[d][b*SEQ+t]
__device__ __half g_Sh[NBATCH * SEQ * SEQ];    // causal scores, fp16
__device__ __half g_Oh[TOK * DM];              // attention out / 512, fp16
__device__ __half g_Wh[NVOCAB * DM];           // fp16 wo
__device__ __half g_Wqk[2 * DM * DM];          // [wq; wk] fp16
__device__ __half g_Wv[DM * DM];
__device__ float  g_bqk[2 * DM];               // [bq; bk]
__device__ float  g_P1[TOK * DM];              // AV partials / logits tail partials
__device__ float  g_P2[2048 * DM];             // AV partial (seg1, rows i>=8), f32

__device__ __forceinline__ uint32_t smem_u32(const void* p) {
    uint32_t a;
    asm("{ .reg .u64 t; cvta.to.shared.u64 t, %1; cvt.u32.u64 %0, t; }" : "=r"(a) : "l"(p));
    return a;
}

__device__ __forceinline__ void mma16h(float* c, const uint32_t* a, const uint32_t* b) {
    asm volatile(
        "mma.sync.aligned.m16n8k16.row.col.f32.f16.f16.f32 "
        "{%0,%1,%2,%3}, {%4,%5,%6,%7}, {%8,%9}, {%0,%1,%2,%3};\n"
        : "+f"(c[0]), "+f"(c[1]), "+f"(c[2]), "+f"(c[3])
        : "r"(a[0]), "r"(a[1]), "r"(a[2]), "r"(a[3]), "r"(b[0]), "r"(b[1]));
}

__device__ __forceinline__ void ldsm4(uint32_t* r, uint32_t addr) {
    asm volatile("ldmatrix.sync.aligned.m8n8.x4.shared.b16 {%0,%1,%2,%3}, [%4];"
        : "=r"(r[0]), "=r"(r[1]), "=r"(r[2]), "=r"(r[3]) : "r"(addr));
}

__device__ __forceinline__ void cp16(uint32_t smem, const void* g) {
    asm volatile("cp.async.cg.shared.global [%0], [%1], 16;" :: "r"(smem), "l"(g) : "memory");
}

// ---- tile constants: 128x256 CTA tile, K-chunk 64, 3 stages ----
namespace lh {
constexpr int PITCH     = 144;                // 128B data (64 fp16) + 16B pad
constexpr int A_BYTES   = 128 * PITCH;        // 18432
constexpr int B_BYTES   = 256 * PITCH;        // 36864
constexpr int STG_BYTES = A_BYTES + B_BYTES;  // 55296
constexpr int SMEM_TOT  = 3 * STG_BYTES;      // 165888
}

// ============================================================================
// Unified fp16 NT GEMM, 512 threads, warp tile 64x32 (2x8 warps):
// EPI: 0 = +colbias then elu+1, 2 = causal mask (1D triangular grid),
//      5 = +rowbias.
// ============================================================================
template<int EPI>
__global__ void __launch_bounds__(NTHR, 1)
gemm_h(const __half* __restrict__ A, int lda,
       const __half* __restrict__ B, int ldb,
       const float* __restrict__ bias,
       __half* __restrict__ C, int ldc,
       int K, long long Az, long long Bz, long long Cz)
{
    A += (size_t)blockIdx.z * Az;
    B += (size_t)blockIdx.z * Bz;
    C += (size_t)blockIdx.z * Cz;

    int bm, bn;
    if (EPI == 2) {
        const int t = blockIdx.x;       // 0..71
        int i = 0, c = 0;
        for (;; i++) {
            int ci = (i >> 1) + 1;
            if (c + ci > t) break;
            c += ci;
        }
        bm = i * 128;
        bn = (t - c) * 256;
    } else {
        bm = blockIdx.x * 128;
        bn = blockIdx.y * 256;
    }

    extern __shared__ char smem[];
    const uint32_t sb = smem_u32(smem);
    const int tid  = threadIdx.x;
    const int lane = tid & 31;
    const int warp = tid >> 5;
    const int wm   = (warp >> 3) * 64;   // 2 warp rows
    const int wn   = (warp & 7) * 32;    // 8 warp cols

    const int g = lane >> 3;
    const uint32_t frOff = (uint32_t)(((lane & 7) + (g & 1) * 8) * lh::PITCH + (g >> 1) * 16);

    float acc[4][4][4];
    #pragma unroll
    for (int mt = 0; mt < 4; mt++)
        #pragma unroll
        for (int nt = 0; nt < 4; nt++)
            #pragma unroll
            for (int r = 0; r < 4; r++) acc[mt][nt][r] = 0.f;

    const __half* Ag = A + (size_t)bm * lda;
    const __half* Bg = B + (size_t)bn * ldb;

    const int nk = K / 64;

    auto load_stage = [&](int st) {
        const uint32_t base = sb + (st % 3) * lh::STG_BYTES;
        const int kb = st * 64;
        #pragma unroll
        for (int i = 0; i < 2; i++) {
            int idx = tid + i * NTHR;
            int row = idx >> 3, ch = idx & 7;
            cp16(base + row * lh::PITCH + ch * 16, Ag + (size_t)row * lda + kb + ch * 8);
        }
        const uint32_t bb = base + lh::A_BYTES;
        #pragma unroll
        for (int i = 0; i < 4; i++) {
            int idx = tid + i * NTHR;
            int row = idx >> 3, ch = idx & 7;
            cp16(bb + row * lh::PITCH + ch * 16, Bg + (size_t)row * ldb + kb + ch * 8);
        }
        asm volatile("cp.async.commit_group;" ::: "memory");
    };

    load_stage(0);
    if (nk > 1) load_stage(1); else asm volatile("cp.async.commit_group;" ::: "memory");

    for (int ck = 0; ck < nk; ck++) {
        asm volatile("cp.async.wait_group 1;" ::: "memory");
        __syncthreads();
        if (ck + 2 < nk) load_stage(ck + 2);
        else asm volatile("cp.async.commit_group;" ::: "memory");

        const uint32_t sa  = sb + (ck % 3) * lh::STG_BYTES;
        const uint32_t sbb = sa + lh::A_BYTES;
        #pragma unroll
        for (int ks = 0; ks < 4; ks++) {
            uint32_t af[4][4], bf[4][2];
            #pragma unroll
            for (int mt = 0; mt < 4; mt++)
                ldsm4(af[mt], sa + (wm + mt * 16) * lh::PITCH + ks * 32 + frOff);
            #pragma unroll
            for (int p = 0; p < 2; p++) {
                uint32_t t4[4];
                ldsm4(t4, sbb + (wn + p * 16) * lh::PITCH + ks * 32 + frOff);
                bf[2 * p][0]     = t4[0]; bf[2 * p][1]     = t4[2];
                bf[2 * p + 1][0] = t4[1]; bf[2 * p + 1][1] = t4[3];
            }
            #pragma unroll
            for (int mt = 0; mt < 4; mt++)
                #pragma unroll
                for (int nt = 0; nt < 4; nt++)
                    mma16h(acc[mt][nt], af[mt], bf[nt]);
        }
    }

    #pragma unroll
    for (int mt = 0; mt < 4; mt++) {
        #pragma unroll
        for (int nt = 0; nt < 4; nt++) {
            int r = bm + wm + mt * 16 + (lane >> 2);
            int c = bn + wn + nt * 8 + ((lane & 3) << 1);
            float v[4] = {acc[mt][nt][0], acc[mt][nt][1], acc[mt][nt][2], acc[mt][nt][3]};
            if (EPI == 0) {
                float b0 = bias[c], b1 = bias[c + 1];
                v[0] += b0; v[1] += b1; v[2] += b0; v[3] += b1;
                #pragma unroll
                for (int j = 0; j < 4; j++)
                    v[j] = (v[j] > 0.f) ? (v[j] + 1.f) : expf(v[j]);
            } else if (EPI == 5) {
                float b0 = bias[r], b1 = bias[r + 8];
                v[0] += b0; v[1] += b0; v[2] += b1; v[3] += b1;
            } else if (EPI == 2) {
                if (c     > r)     v[0] = 0.f;
                if (c + 1 > r)     v[1] = 0.f;
                if (c     > r + 8) v[2] = 0.f;
                if (c + 1 > r + 8) v[3] = 0.f;
            }
            *(__half2*)&C[(size_t)r * ldc + c]       = __floats2half2_rn(v[0], v[1]);
            *(__half2*)&C[(size_t)(r + 8) * ldc + c] = __floats2half2_rn(v[2], v[3]);
        }
    }
}

// ============================================================================
// Split-K AV kernel (as R14): O_partials = S @ Vt^T per batch, triangular K.
// ============================================================================
__global__ void __launch_bounds__(NTHR, 1)
av_split(const __half* __restrict__ S, const __half* __restrict__ Vt,
         float* __restrict__ P1, float* __restrict__ P2)
{
    const int b   = blockIdx.x;
    const int grp = b & 7;
    const int s   = b >> 3;          // 0..23, sorted desc by length
    const int bn  = (grp >> 1) * 256;
    const int z   = grp & 1;

    int i, kb0, len, buf;
    if (s < 8)            { i = 8 + s;          kb0 = 0;  len = 16;            buf = 0; }
    else if ((s & 1) == 0){ i = (22 - s) >> 1;  kb0 = 0;  len = 2 * (i + 1);   buf = 0;
                            if (len > 16) len = 16; }
    else                  { i = (39 - s) >> 1;  kb0 = 16; len = 2 * (i + 1) - 16; buf = 1; }

    const int bm = i * 128;

    extern __shared__ char smem[];
    const uint32_t sb = smem_u32(smem);
    const int tid  = threadIdx.x;
    const int lane = tid & 31;
    const int warp = tid >> 5;
    const int wm   = (warp >> 3) * 64;
    const int wn   = (warp & 7) * 32;

    const int g = lane >> 3;
    const uint32_t frOff = (uint32_t)(((lane & 7) + (g & 1) * 8) * lh::PITCH + (g >> 1) * 16);

    float acc[4][4][4];
    #pragma unroll
    for (int mt = 0; mt < 4; mt++)
        #pragma unroll
        for (int nt = 0; nt < 4; nt++)
            #pragma unroll
            for (int r = 0; r < 4; r++) acc[mt][nt][r] = 0.f;

    const __half* Ag = S  + (size_t)z * SEQ * SEQ + (size_t)bm * SEQ;
    const __half* Bg = Vt + (size_t)bn * TOK + (size_t)z * SEQ;

    auto load_stage = [&](int st) {
        const uint32_t base = sb + (st % 3) * lh::STG_BYTES;
        const int kb = (kb0 + st) * 64;
        #pragma unroll
        for (int ii = 0; ii < 2; ii++) {
            int idx = tid + ii * NTHR;
            int row = idx >> 3, ch = idx & 7;
            cp16(base + row * lh::PITCH + ch * 16, Ag + (size_t)row * SEQ + kb + ch * 8);
        }
        const uint32_t bb = base + lh::A_BYTES;
        #pragma unroll
        for (int ii = 0; ii < 4; ii++) {
            int idx = tid + ii * NTHR;
            int row = idx >> 3, ch = idx & 7;
            cp16(bb + row * lh::PITCH + ch * 16, Bg + (size_t)row * TOK + kb + ch * 8);
        }
        asm volatile("cp.async.commit_group;" ::: "memory");
    };

    load_stage(0);
    if (len > 1) load_stage(1); else asm volatile("cp.async.commit_group;" ::: "memory");

    for (int ck = 0; ck < len; ck++) {
        asm volatile("cp.async.wait_group 1;" ::: "memory");
        __syncthreads();
        if (ck + 2 < len) load_stage(ck + 2);
        else asm volatile("cp.async.commit_group;" ::: "memory");

        const uint32_t sa  = sb + (ck % 3) * lh::STG_BYTES;
        const uint32_t sbb = sa + lh::A_BYTES;
        #pragma unroll
        for (int ks = 0; ks < 4; ks++) {
            uint32_t af[4][4], bf[4][2];
            #pragma unroll
            for (int mt = 0; mt < 4; mt++)
                ldsm4(af[mt], sa + (wm + mt * 16) * lh::PITCH + ks * 32 + frOff);
            #pragma unroll
            for (int p = 0; p < 2; p++) {
                uint32_t t4[4];
                ldsm4(t4, sbb + (wn + p * 16) * lh::PITCH + ks * 32 + frOff);
                bf[2 * p][0]     = t4[0]; bf[2 * p][1]     = t4[2];
                bf[2 * p + 1][0] = t4[1]; bf[2 * p + 1][1] = t4[3];
            }
            #pragma unroll
            for (int mt = 0; mt < 4; mt++)
                #pragma unroll
                for (int nt = 0; nt < 4; nt++)
                    mma16h(acc[mt][nt], af[mt], bf[nt]);
        }
    }

    float* P = buf ? P2 : P1;
    const size_t rowbase = buf ? (size_t)(z * 1024 + (i - 8) * 128)
                               : (size_t)(z * 2048 + i * 128);
    #pragma unroll
    for (int mt = 0; mt < 4; mt++) {
        #pragma unroll
        for (int nt = 0; nt < 4; nt++) {
            size_t r = rowbase + wm + mt * 16 + (lane >> 2);
            int    c = bn + wn + nt * 8 + ((lane & 3) << 1);
            *(float2*)&P[r * DM + c]       = make_float2(acc[mt][nt][0], acc[mt][nt][1]);
            *(float2*)&P[(r + 8) * DM + c] = make_float2(acc[mt][nt][2], acc[mt][nt][3]);
        }
    }
}

// Combine: Oh = fp16((P1 + P2[if row-block >= 8]) / 512)
__global__ void __launch_bounds__(256)
av_combine(const float* __restrict__ P1, const float* __restrict__ P2,
           __half* __restrict__ Oh)
{
    size_t flat = ((size_t)blockIdx.x * 256 + threadIdx.x) * 4;
    int t = (int)(flat >> 10);
    int d = (int)(flat & 1023);
    int z = t >> 11;
    int r = t & 2047;
    float4 v = *(const float4*)(P1 + flat);
    if (r >= 1024) {
        const float4 w = *(const float4*)(P2 + (size_t)(z * 1024 + r - 1024) * DM + d);
        v.x += w.x; v.y += w.y; v.z += w.z; v.w += w.w;
    }
    __half2 h0 = __floats2half2_rn(v.x * O_SCALE_INV, v.y * O_SCALE_INV);
    __half2 h1 = __floats2half2_rn(v.z * O_SCALE_INV, v.w * O_SCALE_INV);
    uint2 u;
    u.x = *(uint32_t*)&h0;
    u.y = *(uint32_t*)&h1;
    *(uint2*)(Oh + flat) = u;
}

// ============================================================================
// PERSISTENT fp16 logits GEMM with balanced remainder:
//   q = ntiles / gridsz full tiles per CTA (tiles [0, q*gridsz)),
//   rem = ntiles - q*gridsz remainder tiles, each split into two K=512
//   half-segments (8 chunks) assigned to bids [0, 2*rem); partials -> Ph.
// Tile map: tile t -> bm = (t % 32)*128, bn = (t / 32)*256.
// ============================================================================
__global__ void __launch_bounds__(NTHR, 1)
logits_persist(const __half* __restrict__ A, const __half* __restrict__ B,
               const float* __restrict__ bias, float* __restrict__ C,
               float* __restrict__ Ph, int gridsz, int q, int rem)
{
    extern __shared__ char smem[];
    const uint32_t sb = smem_u32(smem);
    const int tid  = threadIdx.x;
    const int lane = tid & 31;
    const int warp = tid >> 5;
    const int wm   = (warp >> 3) * 64;
    const int wn   = (warp & 7) * 32;
    const int bid  = blockIdx.x;

    const int g = lane >> 3;
    const uint32_t frOff = (uint32_t)(((lane & 7) + (g & 1) * 8) * lh::PITCH + (g >> 1) * 16);

    const int q16 = q * 16;
    const bool hasSeg = (bid < 2 * rem);
    const int NC = q16 + (hasSeg ? 8 : 0);

    float acc[4][4][4];
    #pragma unroll
    for (int mt = 0; mt < 4; mt++)
        #pragma unroll
        for (int nt = 0; nt < 4; nt++)
            #pragma unroll
            for (int r = 0; r < 4; r++) acc[mt][nt][r] = 0.f;

    auto load_chunk = [&](int cg) {
        int tile, kb;
        if (cg < q16) {
            tile = bid + (cg >> 4) * gridsz;
            kb = (cg & 15) << 6;
        } else {
            tile = q * gridsz + (bid >> 1);
            kb = (((bid & 1) << 3) + (cg - q16)) << 6;
        }
        const int bm = (tile & 31) << 7;
        const int bn = (tile >> 5) << 8;
        const __half* Ag = A + (size_t)bm * DM + kb;
        const __half* Bg = B + (size_t)bn * DM + kb;
        const uint32_t base = sb + (cg % 3) * lh::STG_BYTES;
        #pragma unroll
        for (int i = 0; i < 2; i++) {
            int idx = tid + i * NTHR;
            int row = idx >> 3, ch = idx & 7;
            cp16(base + row * lh::PITCH + ch * 16, Ag + (size_t)row * DM + ch * 8);
        }
        const uint32_t bb = base + lh::A_BYTES;
        #pragma unroll
        for (int i = 0; i < 4; i++) {
            int idx = tid + i * NTHR;
            int row = idx >> 3, ch = idx & 7;
            cp16(bb + row * lh::PITCH + ch * 16, Bg + (size_t)row * DM + ch * 8);
        }
        asm volatile("cp.async.commit_group;" ::: "memory");
    };

    load_chunk(0); load_chunk(1);   // NC >= 16 always

    for (int cg = 0; cg < NC; cg++) {
        asm volatile("cp.async.wait_group 1;" ::: "memory");
        __syncthreads();
        if (cg + 2 < NC) load_chunk(cg + 2);
        else asm volatile("cp.async.commit_group;" ::: "memory");

        const uint32_t sa  = sb + (cg % 3) * lh::STG_BYTES;
        const uint32_t sbb = sa + lh::A_BYTES;
        #pragma unroll
        for (int ks = 0; ks < 4; ks++) {
            uint32_t af[4][4], bf[4][2];
            #pragma unroll
            for (int mt = 0; mt < 4; mt++)
                ldsm4(af[mt], sa + (wm + mt * 16) * lh::PITCH + ks * 32 + frOff);
            #pragma unroll
            for (int p = 0; p < 2; p++) {
                uint32_t t4[4];
                ldsm4(t4, sbb + (wn + p * 16) * lh::PITCH + ks * 32 + frOff);
                bf[2 * p][0]     = t4[0]; bf[2 * p][1]     = t4[2];
                bf[2 * p + 1][0] = t4[1]; bf[2 * p + 1][1] = t4[3];
            }
            #pragma unroll
            for (int mt = 0; mt < 4; mt++)
                #pragma unroll
                for (int nt = 0; nt < 4; nt++)
                    mma16h(acc[mt][nt], af[mt], bf[nt]);
        }

        if (cg < q16) {
            if ((cg & 15) == 15) {
                const int tile = bid + (cg >> 4) * gridsz;
                const int bm = (tile & 31) << 7;
                const int bn = (tile >> 5) << 8;
                #pragma unroll
                for (int mt = 0; mt < 4; mt++) {
                    #pragma unroll
                    for (int nt = 0; nt < 4; nt++) {
                        int r = bm + wm + mt * 16 + (lane >> 2);
                        int c = bn + wn + nt * 8 + ((lane & 3) << 1);
                        const float2 bv = *(const float2*)(bias + c);
                        *(float2*)&C[(size_t)r * NVOCAB + c] = make_float2(
                            acc[mt][nt][0] * O_SCALE + bv.x,
                            acc[mt][nt][1] * O_SCALE + bv.y);
                        *(float2*)&C[(size_t)(r + 8) * NVOCAB + c] = make_float2(
                            acc[mt][nt][2] * O_SCALE + bv.x,
                            acc[mt][nt][3] * O_SCALE + bv.y);
                        acc[mt][nt][0] = 0.f; acc[mt][nt][1] = 0.f;
                        acc[mt][nt][2] = 0.f; acc[mt][nt][3] = 0.f;
                    }
                }
            }
        } else if (cg == NC - 1) {
            // seg done: store f32 partial tile [128][256] to Ph + bid*32768
            float* P = Ph + (size_t)bid * 32768;
            #pragma unroll
            for (int mt = 0; mt < 4; mt++) {
                #pragma unroll
                for (int nt = 0; nt < 4; nt++) {
                    int r = wm + mt * 16 + (lane >> 2);
                    int c = wn + nt * 8 + ((lane & 3) << 1);
                    *(float2*)&P[(size_t)r * 256 + c]       = make_float2(acc[mt][nt][0], acc[mt][nt][1]);
                    *(float2*)&P[(size_t)(r + 8) * 256 + c] = make_float2(acc[mt][nt][2], acc[mt][nt][3]);
                }
            }
        }
    }
}

// Tail combine for the rem split tiles: out = (Ph[2k] + Ph[2k+1]) * 512 + bias
__global__ void __launch_bounds__(256)
logits_tail(const float* __restrict__ Ph, const float* __restrict__ bias,
            float* __restrict__ C, int tile0)
{
    const int k   = blockIdx.x >> 5;                 // remainder tile index
    const int idx = ((blockIdx.x & 31) * 256 + threadIdx.x) * 4;
    const int r = idx >> 8;
    const int c = idx & 255;
    const int tile = tile0 + k;
    const int bm = (tile & 31) << 7;
    const int bn = (tile >> 5) << 8;
    const float4 a = *(const float4*)(Ph + (size_t)(2 * k) * 32768 + idx);
    const float4 b = *(const float4*)(Ph + (size_t)(2 * k + 1) * 32768 + idx);
    const float4 bv = *(const float4*)(bias + bn + c);
    float4 v;
    v.x = (a.x + b.x) * O_SCALE + bv.x;
    v.y = (a.y + b.y) * O_SCALE + bv.y;
    v.z = (a.z + b.z) * O_SCALE + bv.z;
    v.w = (a.w + b.w) * O_SCALE + bv.w;
    *(float4*)&C[(size_t)(bm + r) * NVOCAB + bn + c] = v;
}

// ============================================================================
// Fused prep kernel: wo->fp16, wq/wk/wv->fp16, bias concat, embed gather+cvt.
// ============================================================================
namespace prep {
constexpr int WO_BLK   = NVOCAB * DM / (256 * 16);   // 8000
constexpr int W_BLK    = DM * DM / (256 * 16);       // 256
constexpr int QKV_END  = WO_BLK + 3 * W_BLK;         // 8768
constexpr int GATH_END = QKV_END + TOK;              // 12864
constexpr int TOTAL    = GATH_END + 2 * DM / 256;    // 12872
}

__global__ void __launch_bounds__(256)
prep_all(const float* __restrict__ wo, const float* __restrict__ wq,
         const float* __restrict__ wk, const float* __restrict__ wv,
         const float* __restrict__ bq, const float* __restrict__ bk,
         const int* __restrict__ x, const float* __restrict__ emb,
         __half* __restrict__ Wh, __half* __restrict__ Wqk,
         __half* __restrict__ Wvh, float* __restrict__ bqk,
         __half* __restrict__ eh)
{
    const int b = blockIdx.x;
    if (b < prep::QKV_END) {
        const float* in;
        __half* out;
        size_t base;
        if (b < prep::WO_BLK) {
            in = wo; out = Wh; base = (size_t)b;
        } else {
            int qq = b - prep::WO_BLK;
            int mat = qq / prep::W_BLK;
            base = (size_t)(qq % prep::W_BLK);
            in  = (mat == 0) ? wq : (mat == 1) ? wk : wv;
            out = (mat == 0) ? Wqk : (mat == 1) ? (Wqk + (size_t)DM * DM) : Wvh;
        }
        size_t i = (base * 256 + threadIdx.x) * 16;
        float4 v[4];
        #pragma unroll
        for (int p = 0; p < 4; p++) v[p] = *(const float4*)(in + i + p * 4);
        #pragma unroll
        for (int p = 0; p < 2; p++) {
            __half2 h[4];
            h[0] = __floats2half2_rn(v[2 * p].x,     v[2 * p].y);
            h[1] = __floats2half2_rn(v[2 * p].z,     v[2 * p].w);
            h[2] = __floats2half2_rn(v[2 * p + 1].x, v[2 * p + 1].y);
            h[3] = __floats2half2_rn(v[2 * p + 1].z, v[2 * p + 1].w);
            *(uint4*)(out + i + p * 8) = *(uint4*)h;
        }
    } else if (b < prep::GATH_END) {
        const int t = b - prep::QKV_END;
        const int d = threadIdx.x * 4;
        const float4 v = *(const float4*)(emb + (size_t)x[t] * DM + d);
        __half2 h0 = __floats2half2_rn(v.x, v.y);
        __half2 h1 = __floats2half2_rn(v.z, v.w);
        uint2 u;
        u.x = *(uint32_t*)&h0;
        u.y = *(uint32_t*)&h1;
        *(uint2*)(eh + (size_t)t * DM + d) = u;
    } else {
        int i = (b - prep::GATH_END) * 256 + threadIdx.x;
        bqk[i] = (i < DM) ? bq[i] : bk[i - DM];
    }
}

extern "C" void kernel_launch(void* const* d_in, const int* in_sizes, int n_in,
                              void* d_out, int out_size)
{
    (void)in_sizes; (void)n_in; (void)out_size;
    const int*   x   = (const int*)  d_in[0];
    const float* emb = (const float*)d_in[1];
    const float* wq  = (const float*)d_in[2];
    const float* bq  = (const float*)d_in[3];
    const float* wk  = (const float*)d_in[4];
    const float* bk  = (const float*)d_in[5];
    const float* wv  = (const float*)d_in[6];
    const float* bv  = (const float*)d_in[7];
    const float* wo  = (const float*)d_in[8];
    const float* bo  = (const float*)d_in[9];
    float* out = (float*)d_out;

    __half *eh, *QKh, *Vt, *Sh, *Oh, *Wh, *Wqk, *Wv;
    float *bqk, *P1, *P2;
    cudaGetSymbolAddress((void**)&eh,  g_eh);
    cudaGetSymbolAddress((void**)&QKh, g_QKh);
    cudaGetSymbolAddress((void**)&Vt,  g_Vt);
    cudaGetSymbolAddress((void**)&Sh,  g_Sh);
    cudaGetSymbolAddress((void**)&Oh,  g_Oh);
    cudaGetSymbolAddress((void**)&Wh,  g_Wh);
    cudaGetSymbolAddress((void**)&Wqk, g_Wqk);
    cudaGetSymbolAddress((void**)&Wv,  g_Wv);
    cudaGetSymbolAddress((void**)&bqk, g_bqk);
    cudaGetSymbolAddress((void**)&P1,  g_P1);
    cudaGetSymbolAddress((void**)&P2,  g_P2);

    int nsm = 148;
    cudaDeviceGetAttribute(&nsm, cudaDevAttrMultiProcessorCount, 0);

    cudaFuncSetAttribute(logits_persist,
                         cudaFuncAttributeMaxDynamicSharedMemorySize, lh::SMEM_TOT);
    cudaFuncSetAttribute(av_split,
                         cudaFuncAttributeMaxDynamicSharedMemorySize, lh::SMEM_TOT);
    cudaFuncSetAttribute(gemm_h<0>,
                         cudaFuncAttributeMaxDynamicSharedMemorySize, lh::SMEM_TOT);
    cudaFuncSetAttribute(gemm_h<5>,
                         cudaFuncAttributeMaxDynamicSharedMemorySize, lh::SMEM_TOT);
    cudaFuncSetAttribute(gemm_h<2>,
                         cudaFuncAttributeMaxDynamicSharedMemorySize, lh::SMEM_TOT);

    dim3 thr(256), thrG(NTHR);

    // 0) all conversions / gather / bias concat (serial; overlap proven harmful)
    prep_all<<<prep::TOTAL, thr>>>(wo, wq, wk, wv, bq, bk, x, emb,
                                   Wh, Wqk, Wv, bqk, eh);

    // 1) fused Q+K projection: QKh[4096,2048] = e_h @ Wqk^T, elu+1 + bias
    dim3 gQK(TOK / 128, 2 * DM / 256, 1);
    gemm_h<0><<<gQK, thrG, lh::SMEM_TOT>>>(eh, DM, Wqk, DM, bqk, QKh, 2 * DM, DM, 0, 0, 0);

    // 2) V pre-transposed: Vt[1024,4096] = wv @ e_h^T + bv (row bias)
    dim3 gVt(DM / 128, TOK / 256, 1);
    gemm_h<5><<<gVt, thrG, lh::SMEM_TOT>>>(Wv, DM, eh, DM, bv, Vt, TOK, DM, 0, 0, 0);

    // 3) causal scores: exact triangular grid (72 live tiles per batch, 1 wave)
    dim3 gSc(72, 1, NBATCH);
    gemm_h<2><<<gSc, thrG, lh::SMEM_TOT>>>(
        QKh, 2 * DM, QKh + DM, 2 * DM, nullptr, Sh, SEQ, DM,
        (long long)SEQ * 2 * DM, (long long)SEQ * 2 * DM, (long long)SEQ * SEQ);

    // 4) AV with split-K load balancing (192 segments, longest-first)
    av_split<<<192, thrG, lh::SMEM_TOT>>>(Sh, Vt, P1, P2);
    av_combine<<<TOK * DM / (256 * 4), thr>>>(P1, P2, Oh);

    // 5) logits (persistent, balanced remainder): out = (Oh @ Wh^T)*512 + bo
    const int ntiles = (TOK / 128) * (NVOCAB / 256);   // 4000
    int q   = ntiles / nsm;
    int rem = ntiles - q * nsm;
    if (2 * rem > nsm) { q += 1; rem = 0; }            // safety fallback (unused on 148/152)
    // P1 is free after av_combine; reuse for the remainder half-partials
    logits_persist<<<nsm, thrG, lh::SMEM_TOT>>>(Oh, Wh, bo, out, P1, nsm, q, rem);
    if (rem > 0)
        logits_tail<<<rem * 32, thr>>>(P1, bo, out, q * nsm);
}

// round 17
// speedup vs baseline: 1.0118x; 1.0014x over previous
#include <cuda_runtime.h>
#include <cuda_fp16.h>
#include <cstdint>

namespace {
constexpr int DM     = 1024;
constexpr int SEQ    = 2048;
constexpr int NBATCH = 2;
constexpr int TOK    = SEQ * NBATCH;   // 4096
constexpr int NVOCAB = 32000;
constexpr float O_SCALE     = 512.f;   // O stored as O/512 in fp16 (exact pow2)
constexpr float O_SCALE_INV = 1.f / 512.f;
constexpr int NTHR = 512;              // 16 warps
constexpr int CVT_FLOATS = 256000;     // per converter block: 128 blocks cover 32,768,000
}

// ---- scratch (device globals: allocation-free) ----
__device__ __half g_eh[TOK * DM];              // gathered embeddings, fp16
__device__ __half g_QKh[TOK * 2 * DM];         // [t][0:1024]=Q, [t][1024:2048]=K
__device__ __half g_Vt[DM * TOK];              // V transposed: Vt[d][b*SEQ+t]
__device__ __half g_Sh[NBATCH * SEQ * SEQ];    // causal scores, fp16
__device__ __half g_Oh[TOK * DM];              // attention out / 512, fp16
__device__ __half g_Wh[NVOCAB * DM];           // fp16 wo
__device__ __half g_Wqk[2 * DM * DM];          // [wq; wk] fp16
__device__ __half g_Wv[DM * DM];
__device__ float  g_bqk[2 * DM];               // [bq; bk]
__device__ float  g_P1[TOK * DM];              // AV partials / logits tail partials
__device__ float  g_P2[2048 * DM];             // AV partial (seg1, rows i>=8), f32

__device__ __forceinline__ uint32_t smem_u32(const void* p) {
    uint32_t a;
    asm("{ .reg .u64 t; cvta.to.shared.u64 t, %1; cvt.u32.u64 %0, t; }" : "=r"(a) : "l"(p));
    return a;
}

__device__ __forceinline__ void mma16h(float* c, const uint32_t* a, const uint32_t* b) {
    asm volatile(
        "mma.sync.aligned.m16n8k16.row.col.f32.f16.f16.f32 "
        "{%0,%1,%2,%3}, {%4,%5,%6,%7}, {%8,%9}, {%0,%1,%2,%3};\n"
        : "+f"(c[0]), "+f"(c[1]), "+f"(c[2]), "+f"(c[3])
        : "r"(a[0]), "r"(a[1]), "r"(a[2]), "r"(a[3]), "r"(b[0]), "r"(b[1]));
}

__device__ __forceinline__ void ldsm4(uint32_t* r, uint32_t addr) {
    asm volatile("ldmatrix.sync.aligned.m8n8.x4.shared.b16 {%0,%1,%2,%3}, [%4];"
        : "=r"(r[0]), "=r"(r[1]), "=r"(r[2]), "=r"(r[3]) : "r"(addr));
}

__device__ __forceinline__ void cp16(uint32_t smem, const void* g) {
    asm volatile("cp.async.cg.shared.global [%0], [%1], 16;" :: "r"(smem), "l"(g) : "memory");
}

// Converter block: one 256,000-float slice of wo -> fp16 (512 threads).
__device__ void cvt_block(int id, const float* __restrict__ in,
                          __half* __restrict__ out)
{
    const int tid = threadIdx.x;
    const size_t base = (size_t)id * CVT_FLOATS;
    #pragma unroll 5
    for (int j = 0; j < 125; j++) {
        size_t idx = base + ((size_t)j * NTHR + tid) * 4;
        float4 v = *(const float4*)(in + idx);
        __half2 h0 = __floats2half2_rn(v.x, v.y);
        __half2 h1 = __floats2half2_rn(v.z, v.w);
        uint2 u;
        u.x = *(uint32_t*)&h0;
        u.y = *(uint32_t*)&h1;
        *(uint2*)(out + idx) = u;
    }
}

// ---- tile constants: 128x256 CTA tile, K-chunk 64, 3 stages ----
namespace lh {
constexpr int PITCH     = 144;                // 128B data (64 fp16) + 16B pad
constexpr int A_BYTES   = 128 * PITCH;        // 18432
constexpr int B_BYTES   = 256 * PITCH;        // 36864
constexpr int STG_BYTES = A_BYTES + B_BYTES;  // 55296
constexpr int SMEM_TOT  = 3 * STG_BYTES;      // 165888
}

// ============================================================================
// Unified fp16 NT GEMM, 512 threads, warp tile 64x32 (2x8 warps), 1D tile grid
// with APPENDED wo-converter blocks (blockIdx.x >= ngemm).
// EPI: 0 = +colbias then elu+1, 2 = causal mask (triangular decode, z-batched),
//      5 = +rowbias.
// mtiles: #M-tiles for decode bm=(t%mtiles)*128, bn=(t/mtiles)*256 (EPI!=2).
// ============================================================================
template<int EPI>
__global__ void __launch_bounds__(NTHR, 1)
gemm_h(const __half* __restrict__ A, int lda,
       const __half* __restrict__ B, int ldb,
       const float* __restrict__ bias,
       __half* __restrict__ C, int ldc,
       int K, long long Az, long long Bz, long long Cz,
       int mtiles, int ngemm, int cvbase,
       const float* __restrict__ cvsrc, __half* __restrict__ cvdst)
{
    if ((int)blockIdx.x >= ngemm) {
        int local = (int)blockIdx.x - ngemm;
        if (EPI == 2) local = local + (int)blockIdx.z * 2;   // 2 cvt blocks per z
        cvt_block(cvbase + local, cvsrc, cvdst);
        return;
    }

    A += (size_t)blockIdx.z * Az;
    B += (size_t)blockIdx.z * Bz;
    C += (size_t)blockIdx.z * Cz;

    int bm, bn;
    if (EPI == 2) {
        const int t = blockIdx.x;       // 0..71 triangular
        int i = 0, c = 0;
        for (;; i++) {
            int ci = (i >> 1) + 1;
            if (c + ci > t) break;
            c += ci;
        }
        bm = i * 128;
        bn = (t - c) * 256;
    } else {
        const int t = blockIdx.x;
        bm = (t % mtiles) * 128;
        bn = (t / mtiles) * 256;
    }

    extern __shared__ char smem[];
    const uint32_t sb = smem_u32(smem);
    const int tid  = threadIdx.x;
    const int lane = tid & 31;
    const int warp = tid >> 5;
    const int wm   = (warp >> 3) * 64;   // 2 warp rows
    const int wn   = (warp & 7) * 32;    // 8 warp cols

    const int g = lane >> 3;
    const uint32_t frOff = (uint32_t)(((lane & 7) + (g & 1) * 8) * lh::PITCH + (g >> 1) * 16);

    float acc[4][4][4];
    #pragma unroll
    for (int mt = 0; mt < 4; mt++)
        #pragma unroll
        for (int nt = 0; nt < 4; nt++)
            #pragma unroll
            for (int r = 0; r < 4; r++) acc[mt][nt][r] = 0.f;

    const __half* Ag = A + (size_t)bm * lda;
    const __half* Bg = B + (size_t)bn * ldb;

    const int nk = K / 64;

    auto load_stage = [&](int st) {
        const uint32_t base = sb + (st % 3) * lh::STG_BYTES;
        const int kb = st * 64;
        #pragma unroll
        for (int i = 0; i < 2; i++) {
            int idx = tid + i * NTHR;
            int row = idx >> 3, ch = idx & 7;
            cp16(base + row * lh::PITCH + ch * 16, Ag + (size_t)row * lda + kb + ch * 8);
        }
        const uint32_t bb = base + lh::A_BYTES;
        #pragma unroll
        for (int i = 0; i < 4; i++) {
            int idx = tid + i * NTHR;
            int row = idx >> 3, ch = idx & 7;
            cp16(bb + row * lh::PITCH + ch * 16, Bg + (size_t)row * ldb + kb + ch * 8);
        }
        asm volatile("cp.async.commit_group;" ::: "memory");
    };

    load_stage(0);
    if (nk > 1) load_stage(1); else asm volatile("cp.async.commit_group;" ::: "memory");

    for (int ck = 0; ck < nk; ck++) {
        asm volatile("cp.async.wait_group 1;" ::: "memory");
        __syncthreads();
        if (ck + 2 < nk) load_stage(ck + 2);
        else asm volatile("cp.async.commit_group;" ::: "memory");

        const uint32_t sa  = sb + (ck % 3) * lh::STG_BYTES;
        const uint32_t sbb = sa + lh::A_BYTES;
        #pragma unroll
        for (int ks = 0; ks < 4; ks++) {
            uint32_t af[4][4], bf[4][2];
            #pragma unroll
            for (int mt = 0; mt < 4; mt++)
                ldsm4(af[mt], sa + (wm + mt * 16) * lh::PITCH + ks * 32 + frOff);
            #pragma unroll
            for (int p = 0; p < 2; p++) {
                uint32_t t4[4];
                ldsm4(t4, sbb + (wn + p * 16) * lh::PITCH + ks * 32 + frOff);
                bf[2 * p][0]     = t4[0]; bf[2 * p][1]     = t4[2];
                bf[2 * p + 1][0] = t4[1]; bf[2 * p + 1][1] = t4[3];
            }
            #pragma unroll
            for (int mt = 0; mt < 4; mt++)
                #pragma unroll
                for (int nt = 0; nt < 4; nt++)
                    mma16h(acc[mt][nt], af[mt], bf[nt]);
        }
    }

    #pragma unroll
    for (int mt = 0; mt < 4; mt++) {
        #pragma unroll
        for (int nt = 0; nt < 4; nt++) {
            int r = bm + wm + mt * 16 + (lane >> 2);
            int c = bn + wn + nt * 8 + ((lane & 3) << 1);
            float v[4] = {acc[mt][nt][0], acc[mt][nt][1], acc[mt][nt][2], acc[mt][nt][3]};
            if (EPI == 0) {
                float b0 = bias[c], b1 = bias[c + 1];
                v[0] += b0; v[1] += b1; v[2] += b0; v[3] += b1;
                #pragma unroll
                for (int j = 0; j < 4; j++)
                    v[j] = (v[j] > 0.f) ? (v[j] + 1.f) : expf(v[j]);
            } else if (EPI == 5) {
                float b0 = bias[r], b1 = bias[r + 8];
                v[0] += b0; v[1] += b0; v[2] += b1; v[3] += b1;
            } else if (EPI == 2) {
                if (c     > r)     v[0] = 0.f;
                if (c + 1 > r)     v[1] = 0.f;
                if (c     > r + 8) v[2] = 0.f;
                if (c + 1 > r + 8) v[3] = 0.f;
            }
            *(__half2*)&C[(size_t)r * ldc + c]       = __floats2half2_rn(v[0], v[1]);
            *(__half2*)&C[(size_t)(r + 8) * ldc + c] = __floats2half2_rn(v[2], v[3]);
        }
    }
}

// ============================================================================
// Split-K AV kernel + appended converter blocks (blockIdx.x >= 192).
// ============================================================================
__global__ void __launch_bounds__(NTHR, 1)
av_split(const __half* __restrict__ S, const __half* __restrict__ Vt,
         float* __restrict__ P1, float* __restrict__ P2,
         int cvbase, const float* __restrict__ cvsrc, __half* __restrict__ cvdst)
{
    if ((int)blockIdx.x >= 192) {
        cvt_block(cvbase + (int)blockIdx.x - 192, cvsrc, cvdst);
        return;
    }

    const int b   = blockIdx.x;
    const int grp = b & 7;
    const int s   = b >> 3;          // 0..23, sorted desc by length
    const int bn  = (grp >> 1) * 256;
    const int z   = grp & 1;

    int i, kb0, len, buf;
    if (s < 8)            { i = 8 + s;          kb0 = 0;  len = 16;            buf = 0; }
    else if ((s & 1) == 0){ i = (22 - s) >> 1;  kb0 = 0;  len = 2 * (i + 1);   buf = 0;
                            if (len > 16) len = 16; }
    else                  { i = (39 - s) >> 1;  kb0 = 16; len = 2 * (i + 1) - 16; buf = 1; }

    const int bm = i * 128;

    extern __shared__ char smem[];
    const uint32_t sb = smem_u32(smem);
    const int tid  = threadIdx.x;
    const int lane = tid & 31;
    const int warp = tid >> 5;
    const int wm   = (warp >> 3) * 64;
    const int wn   = (warp & 7) * 32;

    const int g = lane >> 3;
    const uint32_t frOff = (uint32_t)(((lane & 7) + (g & 1) * 8) * lh::PITCH + (g >> 1) * 16);

    float acc[4][4][4];
    #pragma unroll
    for (int mt = 0; mt < 4; mt++)
        #pragma unroll
        for (int nt = 0; nt < 4; nt++)
            #pragma unroll
            for (int r = 0; r < 4; r++) acc[mt][nt][r] = 0.f;

    const __half* Ag = S  + (size_t)z * SEQ * SEQ + (size_t)bm * SEQ;
    const __half* Bg = Vt + (size_t)bn * TOK + (size_t)z * SEQ;

    auto load_stage = [&](int st) {
        const uint32_t base = sb + (st % 3) * lh::STG_BYTES;
        const int kb = (kb0 + st) * 64;
        #pragma unroll
        for (int ii = 0; ii < 2; ii++) {
            int idx = tid + ii * NTHR;
            int row = idx >> 3, ch = idx & 7;
            cp16(base + row * lh::PITCH + ch * 16, Ag + (size_t)row * SEQ + kb + ch * 8);
        }
        const uint32_t bb = base + lh::A_BYTES;
        #pragma unroll
        for (int ii = 0; ii < 4; ii++) {
            int idx = tid + ii * NTHR;
            int row = idx >> 3, ch = idx & 7;
            cp16(bb + row * lh::PITCH + ch * 16, Bg + (size_t)row * TOK + kb + ch * 8);
        }
        asm volatile("cp.async.commit_group;" ::: "memory");
    };

    load_stage(0);
    if (len > 1) load_stage(1); else asm volatile("cp.async.commit_group;" ::: "memory");

    for (int ck = 0; ck < len; ck++) {
        asm volatile("cp.async.wait_group 1;" ::: "memory");
        __syncthreads();
        if (ck + 2 < len) load_stage(ck + 2);
        else asm volatile("cp.async.commit_group;" ::: "memory");

        const uint32_t sa  = sb + (ck % 3) * lh::STG_BYTES;
        const uint32_t sbb = sa + lh::A_BYTES;
        #pragma unroll
        for (int ks = 0; ks < 4; ks++) {
            uint32_t af[4][4], bf[4][2];
            #pragma unroll
            for (int mt = 0; mt < 4; mt++)
                ldsm4(af[mt], sa + (wm + mt * 16) * lh::PITCH + ks * 32 + frOff);
            #pragma unroll
            for (int p = 0; p < 2; p++) {
                uint32_t t4[4];
                ldsm4(t4, sbb + (wn + p * 16) * lh::PITCH + ks * 32 + frOff);
                bf[2 * p][0]     = t4[0]; bf[2 * p][1]     = t4[2];
                bf[2 * p + 1][0] = t4[1]; bf[2 * p + 1][1] = t4[3];
            }
            #pragma unroll
            for (int mt = 0; mt < 4; mt++)
                #pragma unroll
                for (int nt = 0; nt < 4; nt++)
                    mma16h(acc[mt][nt], af[mt], bf[nt]);
        }
    }

    float* P = buf ? P2 : P1;
    const size_t rowbase = buf ? (size_t)(z * 1024 + (i - 8) * 128)
                               : (size_t)(z * 2048 + i * 128);
    #pragma unroll
    for (int mt = 0; mt < 4; mt++) {
        #pragma unroll
        for (int nt = 0; nt < 4; nt++) {
            size_t r = rowbase + wm + mt * 16 + (lane >> 2);
            int    c = bn + wn + nt * 8 + ((lane & 3) << 1);
            *(float2*)&P[r * DM + c]       = make_float2(acc[mt][nt][0], acc[mt][nt][1]);
            *(float2*)&P[(r + 8) * DM + c] = make_float2(acc[mt][nt][2], acc[mt][nt][3]);
        }
    }
}

// Combine: Oh = fp16((P1 + P2[if row-block >= 8]) / 512)
__global__ void __launch_bounds__(256)
av_combine(const float* __restrict__ P1, const float* __restrict__ P2,
           __half* __restrict__ Oh)
{
    size_t flat = ((size_t)blockIdx.x * 256 + threadIdx.x) * 4;
    int t = (int)(flat >> 10);
    int d = (int)(flat & 1023);
    int z = t >> 11;
    int r = t & 2047;
    float4 v = *(const float4*)(P1 + flat);
    if (r >= 1024) {
        const float4 w = *(const float4*)(P2 + (size_t)(z * 1024 + r - 1024) * DM + d);
        v.x += w.x; v.y += w.y; v.z += w.z; v.w += w.w;
    }
    __half2 h0 = __floats2half2_rn(v.x * O_SCALE_INV, v.y * O_SCALE_INV);
    __half2 h1 = __floats2half2_rn(v.z * O_SCALE_INV, v.w * O_SCALE_INV);
    uint2 u;
    u.x = *(uint32_t*)&h0;
    u.y = *(uint32_t*)&h1;
    *(uint2*)(Oh + flat) = u;
}

// ============================================================================
// PERSISTENT fp16 logits GEMM with balanced remainder (as R16).
// ============================================================================
__global__ void __launch_bounds__(NTHR, 1)
logits_persist(const __half* __restrict__ A, const __half* __restrict__ B,
               const float* __restrict__ bias, float* __restrict__ C,
               float* __restrict__ Ph, int gridsz, int q, int rem)
{
    extern __shared__ char smem[];
    const uint32_t sb = smem_u32(smem);
    const int tid  = threadIdx.x;
    const int lane = tid & 31;
    const int warp = tid >> 5;
    const int wm   = (warp >> 3) * 64;
    const int wn   = (warp & 7) * 32;
    const int bid  = blockIdx.x;

    const int g = lane >> 3;
    const uint32_t frOff = (uint32_t)(((lane & 7) + (g & 1) * 8) * lh::PITCH + (g >> 1) * 16);

    const int q16 = q * 16;
    const bool hasSeg = (bid < 2 * rem);
    const int NC = q16 + (hasSeg ? 8 : 0);

    float acc[4][4][4];
    #pragma unroll
    for (int mt = 0; mt < 4; mt++)
        #pragma unroll
        for (int nt = 0; nt < 4; nt++)
            #pragma unroll
            for (int r = 0; r < 4; r++) acc[mt][nt][r] = 0.f;

    auto load_chunk = [&](int cg) {
        int tile, kb;
        if (cg < q16) {
            tile = bid + (cg >> 4) * gridsz;
            kb = (cg & 15) << 6;
        } else {
            tile = q * gridsz + (bid >> 1);
            kb = (((bid & 1) << 3) + (cg - q16)) << 6;
        }
        const int bm = (tile & 31) << 7;
        const int bn = (tile >> 5) << 8;
        const __half* Ag = A + (size_t)bm * DM + kb;
        const __half* Bg = B + (size_t)bn * DM + kb;
        const uint32_t base = sb + (cg % 3) * lh::STG_BYTES;
        #pragma unroll
        for (int i = 0; i < 2; i++) {
            int idx = tid + i * NTHR;
            int row = idx >> 3, ch = idx & 7;
            cp16(base + row * lh::PITCH + ch * 16, Ag + (size_t)row * DM + ch * 8);
        }
        const uint32_t bb = base + lh::A_BYTES;
        #pragma unroll
        for (int i = 0; i < 4; i++) {
            int idx = tid + i * NTHR;
            int row = idx >> 3, ch = idx & 7;
            cp16(bb + row * lh::PITCH + ch * 16, Bg + (size_t)row * DM + ch * 8);
        }
        asm volatile("cp.async.commit_group;" ::: "memory");
    };

    load_chunk(0); load_chunk(1);   // NC >= 16 always

    for (int cg = 0; cg < NC; cg++) {
        asm volatile("cp.async.wait_group 1;" ::: "memory");
        __syncthreads();
        if (cg + 2 < NC) load_chunk(cg + 2);
        else asm volatile("cp.async.commit_group;" ::: "memory");

        const uint32_t sa  = sb + (cg % 3) * lh::STG_BYTES;
        const uint32_t sbb = sa + lh::A_BYTES;
        #pragma unroll
        for (int ks = 0; ks < 4; ks++) {
            uint32_t af[4][4], bf[4][2];
            #pragma unroll
            for (int mt = 0; mt < 4; mt++)
                ldsm4(af[mt], sa + (wm + mt * 16) * lh::PITCH + ks * 32 + frOff);
            #pragma unroll
            for (int p = 0; p < 2; p++) {
                uint32_t t4[4];
                ldsm4(t4, sbb + (wn + p * 16) * lh::PITCH + ks * 32 + frOff);
                bf[2 * p][0]     = t4[0]; bf[2 * p][1]     = t4[2];
                bf[2 * p + 1][0] = t4[1]; bf[2 * p + 1][1] = t4[3];
            }
            #pragma unroll
            for (int mt = 0; mt < 4; mt++)
                #pragma unroll
                for (int nt = 0; nt < 4; nt++)
                    mma16h(acc[mt][nt], af[mt], bf[nt]);
        }

        if (cg < q16) {
            if ((cg & 15) == 15) {
                const int tile = bid + (cg >> 4) * gridsz;
                const int bm = (tile & 31) << 7;
                const int bn = (tile >> 5) << 8;
                #pragma unroll
                for (int mt = 0; mt < 4; mt++) {
                    #pragma unroll
                    for (int nt = 0; nt < 4; nt++) {
                        int r = bm + wm + mt * 16 + (lane >> 2);
                        int c = bn + wn + nt * 8 + ((lane & 3) << 1);
                        const float2 bv = *(const float2*)(bias + c);
                        *(float2*)&C[(size_t)r * NVOCAB + c] = make_float2(
                            acc[mt][nt][0] * O_SCALE + bv.x,
                            acc[mt][nt][1] * O_SCALE + bv.y);
                        *(float2*)&C[(size_t)(r + 8) * NVOCAB + c] = make_float2(
                            acc[mt][nt][2] * O_SCALE + bv.x,
                            acc[mt][nt][3] * O_SCALE + bv.y);
                        acc[mt][nt][0] = 0.f; acc[mt][nt][1] = 0.f;
                        acc[mt][nt][2] = 0.f; acc[mt][nt][3] = 0.f;
                    }
                }
            }
        } else if (cg == NC - 1) {
            float* P = Ph + (size_t)bid * 32768;
            #pragma unroll
            for (int mt = 0; mt < 4; mt++) {
                #pragma unroll
                for (int nt = 0; nt < 4; nt++) {
                    int r = wm + mt * 16 + (lane >> 2);
                    int c = wn + nt * 8 + ((lane & 3) << 1);
                    *(float2*)&P[(size_t)r * 256 + c]       = make_float2(acc[mt][nt][0], acc[mt][nt][1]);
                    *(float2*)&P[(size_t)(r + 8) * 256 + c] = make_float2(acc[mt][nt][2], acc[mt][nt][3]);
                }
            }
        }
    }
}

// Tail combine for the rem split tiles: out = (Ph[2k] + Ph[2k+1]) * 512 + bias
__global__ void __launch_bounds__(256)
logits_tail(const float* __restrict__ Ph, const float* __restrict__ bias,
            float* __restrict__ C, int tile0)
{
    const int k   = blockIdx.x >> 5;
    const int idx = ((blockIdx.x & 31) * 256 + threadIdx.x) * 4;
    const int r = idx >> 8;
    const int c = idx & 255;
    const int tile = tile0 + k;
    const int bm = (tile & 31) << 7;
    const int bn = (tile >> 5) << 8;
    const float4 a = *(const float4*)(Ph + (size_t)(2 * k) * 32768 + idx);
    const float4 b = *(const float4*)(Ph + (size_t)(2 * k + 1) * 32768 + idx);
    const float4 bv = *(const float4*)(bias + bn + c);
    float4 v;
    v.x = (a.x + b.x) * O_SCALE + bv.x;
    v.y = (a.y + b.y) * O_SCALE + bv.y;
    v.z = (a.z + b.z) * O_SCALE + bv.z;
    v.w = (a.w + b.w) * O_SCALE + bv.w;
    *(float4*)&C[(size_t)(bm + r) * NVOCAB + bn + c] = v;
}

// ============================================================================
// Fused prep kernel (wo removed — converted inside the GEMM chain):
// wq/wk/wv->fp16, bias concat, embed gather+cvt.
// ============================================================================
namespace prep {
constexpr int W_BLK    = DM * DM / (256 * 16);       // 256
constexpr int QKV_END  = 3 * W_BLK;                  // 768
constexpr int GATH_END = QKV_END + TOK;              // 4864
constexpr int TOTAL    = GATH_END + 2 * DM / 256;    // 4872
}

__global__ void __launch_bounds__(256)
prep_small(const float* __restrict__ wq, const float* __restrict__ wk,
           const float* __restrict__ wv,
           const float* __restrict__ bq, const float* __restrict__ bk,
           const int* __restrict__ x, const float* __restrict__ emb,
           __half* __restrict__ Wqk, __half* __restrict__ Wvh,
           float* __restrict__ bqk, __half* __restrict__ eh)
{
    const int b = blockIdx.x;
    if (b < prep::QKV_END) {
        int mat = b / prep::W_BLK;
        size_t base = (size_t)(b % prep::W_BLK);
        const float* in  = (mat == 0) ? wq : (mat == 1) ? wk : wv;
        __half* out = (mat == 0) ? Wqk : (mat == 1) ? (Wqk + (size_t)DM * DM) : Wvh;
        size_t i = (base * 256 + threadIdx.x) * 16;
        float4 v[4];
        #pragma unroll
        for (int p = 0; p < 4; p++) v[p] = *(const float4*)(in + i + p * 4);
        #pragma unroll
        for (int p = 0; p < 2; p++) {
            __half2 h[4];
            h[0] = __floats2half2_rn(v[2 * p].x,     v[2 * p].y);
            h[1] = __floats2half2_rn(v[2 * p].z,     v[2 * p].w);
            h[2] = __floats2half2_rn(v[2 * p + 1].x, v[2 * p + 1].y);
            h[3] = __floats2half2_rn(v[2 * p + 1].z, v[2 * p + 1].w);
            *(uint4*)(out + i + p * 8) = *(uint4*)h;
        }
    } else if (b < prep::GATH_END) {
        const int t = b - prep::QKV_END;
        const int d = threadIdx.x * 4;
        const float4 v = *(const float4*)(emb + (size_t)x[t] * DM + d);
        __half2 h0 = __floats2half2_rn(v.x, v.y);
        __half2 h1 = __floats2half2_rn(v.z, v.w);
        uint2 u;
        u.x = *(uint32_t*)&h0;
        u.y = *(uint32_t*)&h1;
        *(uint2*)(eh + (size_t)t * DM + d) = u;
    } else {
        int i = (b - prep::GATH_END) * 256 + threadIdx.x;
        bqk[i] = (i < DM) ? bq[i] : bk[i - DM];
    }
}

extern "C" void kernel_launch(void* const* d_in, const int* in_sizes, int n_in,
                              void* d_out, int out_size)
{
    (void)in_sizes; (void)n_in; (void)out_size;
    const int*   x   = (const int*)  d_in[0];
    const float* emb = (const float*)d_in[1];
    const float* wq  = (const float*)d_in[2];
    const float* bq  = (const float*)d_in[3];
    const float* wk  = (const float*)d_in[4];
    const float* bk  = (const float*)d_in[5];
    const float* wv  = (const float*)d_in[6];
    const float* bv  = (const float*)d_in[7];
    const float* wo  = (const float*)d_in[8];
    const float* bo  = (const float*)d_in[9];
    float* out = (float*)d_out;

    __half *eh, *QKh, *Vt, *Sh, *Oh, *Wh, *Wqk, *Wv;
    float *bqk, *P1, *P2;
    cudaGetSymbolAddress((void**)&eh,  g_eh);
    cudaGetSymbolAddress((void**)&QKh, g_QKh);
    cudaGetSymbolAddress((void**)&Vt,  g_Vt);
    cudaGetSymbolAddress((void**)&Sh,  g_Sh);
    cudaGetSymbolAddress((void**)&Oh,  g_Oh);
    cudaGetSymbolAddress((void**)&Wh,  g_Wh);
    cudaGetSymbolAddress((void**)&Wqk, g_Wqk);
    cudaGetSymbolAddress((void**)&Wv,  g_Wv);
    cudaGetSymbolAddress((void**)&bqk, g_bqk);
    cudaGetSymbolAddress((void**)&P1,  g_P1);
    cudaGetSymbolAddress((void**)&P2,  g_P2);

    int nsm = 148;
    cudaDeviceGetAttribute(&nsm, cudaDevAttrMultiProcessorCount, 0);

    cudaFuncSetAttribute(logits_persist,
                         cudaFuncAttributeMaxDynamicSharedMemorySize, lh::SMEM_TOT);
    cudaFuncSetAttribute(av_split,
                         cudaFuncAttributeMaxDynamicSharedMemorySize, lh::SMEM_TOT);
    cudaFuncSetAttribute(gemm_h<0>,
                         cudaFuncAttributeMaxDynamicSharedMemorySize, lh::SMEM_TOT);
    cudaFuncSetAttribute(gemm_h<5>,
                         cudaFuncAttributeMaxDynamicSharedMemorySize, lh::SMEM_TOT);
    cudaFuncSetAttribute(gemm_h<2>,
                         cudaFuncAttributeMaxDynamicSharedMemorySize, lh::SMEM_TOT);

    dim3 thr(256), thrG(NTHR);

    // 0) small prep (wo conversion now rides inside the GEMM chain's idle SMs)
    prep_small<<<prep::TOTAL, thr>>>(wq, wk, wv, bq, bk, x, emb, Wqk, Wv, bqk, eh);

    // 1) fused Q+K projection (256 tiles, mtiles=32) + 40 wo-cvt blocks (ids 0-39)
    gemm_h<0><<<296, thrG, lh::SMEM_TOT>>>(eh, DM, Wqk, DM, bqk, QKh, 2 * DM, DM,
                                           0, 0, 0, 32, 256, 0, wo, Wh);

    // 2) Vt (128 tiles, mtiles=8) + 20 wo-cvt blocks (ids 40-59)
    gemm_h<5><<<148, thrG, lh::SMEM_TOT>>>(Wv, DM, eh, DM, bv, Vt, TOK, DM,
                                           0, 0, 0, 8, 128, 40, wo, Wh);

    // 3) causal scores (72 triangular tiles/batch) + 2 wo-cvt blocks per z (ids 60-63)
    dim3 gSc(74, 1, NBATCH);
    gemm_h<2><<<gSc, thrG, lh::SMEM_TOT>>>(
        QKh, 2 * DM, QKh + DM, 2 * DM, nullptr, Sh, SEQ, DM,
        (long long)SEQ * 2 * DM, (long long)SEQ * 2 * DM, (long long)SEQ * SEQ,
        0, 72, 60, wo, Wh);

    // 4) AV split-K (192 segments) + 64 wo-cvt blocks (ids 64-127)
    av_split<<<256, thrG, lh::SMEM_TOT>>>(Sh, Vt, P1, P2, 64, wo, Wh);
    av_combine<<<TOK * DM / (256 * 4), thr>>>(P1, P2, Oh);

    // 5) logits (persistent, balanced remainder): out = (Oh @ Wh^T)*512 + bo
    const int ntiles = (TOK / 128) * (NVOCAB / 256);   // 4000
    int q   = ntiles / nsm;
    int rem = ntiles - q * nsm;
    if (2 * rem > nsm) { q += 1; rem = 0; }
    logits_persist<<<nsm, thrG, lh::SMEM_TOT>>>(Oh, Wh, bo, out, P1, nsm, q, rem);
    if (rem > 0)
        logits_tail<<<rem * 32, thr>>>(P1, bo, out, q * nsm);
}